// round 1
// baseline (speedup 1.0000x reference)
#include <cuda_runtime.h>

// Problem constants (fixed by the reference)
#define DVOL   128
#define RES    179
#define NPROJ  10
#define PIX    (RES * RES)          // 32041
#define NPIX   (NPROJ * PIX)        // 320410
#define BW     130                  // padded width (z and x) of the B table
#define BPLANE (BW * BW)            // 16900 float2 per k-plane

// Precomputed plane-pair-averaged, x-paired, zero-padded table:
// B[k][zi][xi] = ( A[k][zi-1][xi-1], A[k][zi-1][xi] )
// where A[k][z][x] = 0.5*(vol[z][k-1][x] + vol[z][k][x]) (vol[.,-1,.] = 0),
// and any out-of-range z/x entry is 0.
__device__ float2 g_B[DVOL * BPLANE];   // 128*130*130*8 B ≈ 17.3 MB

__global__ void build_B_kernel(const float* __restrict__ vol) {
    int t = blockIdx.x * blockDim.x + threadIdx.x;
    const int total = DVOL * BPLANE;
    if (t >= total) return;
    int k   = t / BPLANE;
    int rem = t - k * BPLANE;
    int zi  = rem / BW;
    int xi  = rem - zi * BW;
    int z   = zi - 1;

    float a0 = 0.0f, a1 = 0.0f;
    if (z >= 0 && z < DVOL) {
        const float* pk = vol + (z * DVOL + k) * DVOL;           // plane y=k
        const float* pm = vol + (z * DVOL + (k > 0 ? k - 1 : 0)) * DVOL; // y=k-1
        int x0 = xi - 1;
        int x1 = xi;
        if (x0 >= 0 && x0 < DVOL) {
            float s  = pk[x0];
            float sm = (k > 0) ? pm[x0] : 0.0f;
            a0 = 0.5f * (s + sm);
        }
        if (x1 >= 0 && x1 < DVOL) {
            float s  = pk[x1];
            float sm = (k > 0) ? pm[x1] : 0.0f;
            a1 = 0.5f * (s + sm);
        }
    }
    g_B[t] = make_float2(a0, a1);
}

__global__ void __launch_bounds__(256) project_kernel(
    const float* __restrict__ poses,
    const int*   __restrict__ idx,
    float*       __restrict__ out)
{
    int t = blockIdx.x * blockDim.x + threadIdx.x;
    if (t >= NPIX) return;
    int p   = t / PIX;
    int rem = t - p * PIX;
    int i   = rem / RES;            // detector row  (lin_x / gx)
    int j   = rem - i * RES;        // detector col  (lin_y / gy) — contiguous per lane

    int e = __ldg(&idx[p]);
    float ex = __ldg(&poses[e * 3 + 0]);
    float ey = __ldg(&poses[e * 3 + 1]);
    float ez = __ldg(&poses[e * 3 + 2]);

    float gx = (float)i - 89.5f;
    float gy = (float)j - 89.5f;

    // Unnormalized ray; normalization cancels everywhere except dx.
    float rx = gx - ex;
    float ry = -ey;                  // detector plane is y = 0
    float rz = gy - ez;
    float n  = sqrtf(rx * rx + ry * ry + rz * rz);
    float inv_ry = 1.0f / ry;
    float dxw = fabsf(inv_ry) * n;   // |1/ray_y| for the normalized ray

    // Sample position at plane k (volume index space):
    //   iz (D axis) = p.x + 63.5 = ex + rx*(k-ey)/ry + 63.5  -> bz + k*sz
    //   ix (H axis) = p.z + 63.5 = ez + rz*(k-ey)/ry + 63.5  -> bx + k*sx
    float sz = rx * inv_ry;
    float sx = rz * inv_ry;
    float bz = fmaf(-ey, sz, ex + 63.5f);
    float bx = fmaf(-ey, sx, ez + 63.5f);

    float acc = 0.0f;
    #pragma unroll 4
    for (int k = 0; k < DVOL; ++k) {
        float kf  = (float)k;
        float fz  = fmaf(kf, sz, bz);
        float fx  = fmaf(kf, sx, bx);
        float z0f = floorf(fz);
        float x0f = floorf(fx);
        int z0 = (int)z0f;
        int x0 = (int)x0f;
        // In-range window: z0,x0 in [-1,127]; zero-padded borders handle edges.
        if ((unsigned)(z0 + 1) <= 128u && (unsigned)(x0 + 1) <= 128u) {
            float wz = fz - z0f;
            float wx = fx - x0f;
            const float2* row = g_B + ((k * BW + (z0 + 1)) * BW + (x0 + 1));
            float2 b0 = __ldg(row);        // (A[z0][x0],   A[z0][x0+1])
            float2 b1 = __ldg(row + BW);   // (A[z0+1][x0], A[z0+1][x0+1])
            float v0 = fmaf(wx, b0.y, (1.0f - wx) * b0.x);
            float v1 = fmaf(wx, b1.y, (1.0f - wx) * b1.x);
            acc = fmaf(1.0f - wz, v0, acc);
            acc = fmaf(wz, v1, acc);
        }
    }
    out[t] = acc * dxw;
}

// Tail: reference returns (projections, idx). If the harness expects idx
// appended, write it (cast to float, since __output__ is float32).
__global__ void write_tail_kernel(const int* __restrict__ idx,
                                  float* __restrict__ out, int tail) {
    int t = threadIdx.x;
    if (t < tail) {
        out[NPIX + t] = (t < NPROJ) ? (float)__ldg(&idx[t]) : 0.0f;
    }
}

extern "C" void kernel_launch(void* const* d_in, const int* in_sizes, int n_in,
                              void* d_out, int out_size) {
    const float* vol   = (const float*)d_in[0];   // I_rec: 1*1*128*128*128 f32
    const float* poses = (const float*)d_in[1];   // 50*3 f32
    const int*   idx   = (const int*)d_in[2];     // 10 i32
    float* out = (float*)d_out;

    {
        const int total = DVOL * BPLANE;
        build_B_kernel<<<(total + 255) / 256, 256>>>(vol);
    }
    project_kernel<<<(NPIX + 255) / 256, 256>>>(poses, idx, out);

    if (out_size > NPIX) {
        int tail = out_size - NPIX;
        if (tail > 1024) tail = 1024;
        write_tail_kernel<<<1, 1024>>>(idx, out, tail);
    }
}

// round 2
// speedup vs baseline: 1.0122x; 1.0122x over previous
#include <cuda_runtime.h>

// Problem constants (fixed by the reference)
#define DVOL   128
#define RES    179
#define NPROJ  10
#define PIX    (RES * RES)          // 32041
#define NPIX   (NPROJ * PIX)        // 320410
#define BW     130                  // padded extent of zi/xi (0..129)
#define BPLANE (BW * BW)            // 16900 float4 per k-plane

// 4-corner table:
//   C[k][zi][xi] = ( A[zi-1][xi-1], A[zi-1][xi], A[zi][xi-1], A[zi][xi] )
// where A[z][x] = 0.5*(vol[z][k-1][x] + vol[z][k][x]) (vol[.,-1,.]=0),
// and out-of-range z/x (outside [0,127]) contribute 0.
// One LDG.128 at (k, z0+1, x0+1) yields the full bilinear stencil.
__device__ float4 g_C[DVOL * BPLANE];   // 128*130*130*16B ≈ 34.6 MB (L2-resident)

__global__ void __launch_bounds__(256) build_C_kernel(const float* __restrict__ vol) {
    int t = blockIdx.x * blockDim.x + threadIdx.x;
    const int total = DVOL * BPLANE;
    if (t >= total) return;
    int k   = t / BPLANE;
    int rem = t - k * BPLANE;
    int zi  = rem / BW;
    int xi  = rem - zi * BW;

    int z0 = zi - 1, z1 = zi;
    int x0 = xi - 1, x1 = xi;
    bool zv0 = (unsigned)z0 < 128u, zv1 = (unsigned)z1 < 128u;
    bool xv0 = (unsigned)x0 < 128u, xv1 = (unsigned)x1 < 128u;

    float a00 = 0.f, a01 = 0.f, a10 = 0.f, a11 = 0.f;
    if (zv0) {
        const float* pk = vol + (z0 * DVOL + k) * DVOL;
        const float* pm = vol + (z0 * DVOL + (k > 0 ? k - 1 : 0)) * DVOL;
        if (xv0) a00 = 0.5f * (__ldg(pk + x0) + (k > 0 ? __ldg(pm + x0) : 0.f));
        if (xv1) a01 = 0.5f * (__ldg(pk + x1) + (k > 0 ? __ldg(pm + x1) : 0.f));
    }
    if (zv1) {
        const float* pk = vol + (z1 * DVOL + k) * DVOL;
        const float* pm = vol + (z1 * DVOL + (k > 0 ? k - 1 : 0)) * DVOL;
        if (xv0) a10 = 0.5f * (__ldg(pk + x0) + (k > 0 ? __ldg(pm + x0) : 0.f));
        if (xv1) a11 = 0.5f * (__ldg(pk + x1) + (k > 0 ? __ldg(pm + x1) : 0.f));
    }
    g_C[t] = make_float4(a00, a01, a10, a11);
}

__global__ void __launch_bounds__(256) project_kernel(
    const float* __restrict__ poses,
    const int*   __restrict__ idx,
    float*       __restrict__ out)
{
    int t = blockIdx.x * blockDim.x + threadIdx.x;
    if (t >= NPIX) return;
    int p   = t / PIX;
    int rem = t - p * PIX;
    int i   = rem / RES;            // detector row  (gx)
    int j   = rem - i * RES;        // detector col  (gy) — contiguous per lane

    int e = __ldg(&idx[p]);
    float ex = __ldg(&poses[e * 3 + 0]);
    float ey = __ldg(&poses[e * 3 + 1]);
    float ez = __ldg(&poses[e * 3 + 2]);

    float gx = (float)i - 89.5f;
    float gy = (float)j - 89.5f;

    // Unnormalized ray; normalization cancels everywhere except dx weight.
    float rx = gx - ex;
    float ry = -ey;                  // detector plane is y = 0
    float rz = gy - ez;
    float n  = sqrtf(rx * rx + ry * ry + rz * rz);
    float inv_ry = 1.0f / ry;
    float dxw = fabsf(inv_ry) * n;

    // Sample position at plane k (volume index space), linear in k:
    //   fz = bz + k*sz   (D axis),   fx = bx + k*sx   (H axis)
    float sz = rx * inv_ry;
    float sx = rz * inv_ry;
    float bz = fmaf(-ey, sz, ex + 63.5f);
    float bx = fmaf(-ey, sx, ez + 63.5f);

    // Trim k to the (conservative) interval where fz,fx are inside [-1.5, 129.5];
    // the exact per-iteration predicate below handles the boundary precisely.
    float lo_k = 0.0f, hi_k = 127.0f;
    {
        if (fabsf(sz) > 1e-12f) {
            float is = 1.0f / sz;
            float t0 = (-1.5f - bz) * is, t1 = (129.5f - bz) * is;
            lo_k = fmaxf(lo_k, fminf(t0, t1));
            hi_k = fminf(hi_k, fmaxf(t0, t1));
        } else if (bz < -1.5f || bz > 129.5f) { lo_k = 1.0f; hi_k = 0.0f; }
        if (fabsf(sx) > 1e-12f) {
            float is = 1.0f / sx;
            float t0 = (-1.5f - bx) * is, t1 = (129.5f - bx) * is;
            lo_k = fmaxf(lo_k, fminf(t0, t1));
            hi_k = fminf(hi_k, fmaxf(t0, t1));
        } else if (bx < -1.5f || bx > 129.5f) { lo_k = 1.0f; hi_k = 0.0f; }
    }
    int kmin = max(0, (int)floorf(lo_k));
    int kmax = min(DVOL - 1, (int)ceilf(hi_k));

    float acc = 0.0f;
    float kf  = (float)kmin;
    int kbase = kmin * BPLANE;
    #pragma unroll 4
    for (int k = kmin; k <= kmax; ++k, kf += 1.0f, kbase += BPLANE) {
        float fz  = fmaf(kf, sz, bz);
        float fx  = fmaf(kf, sx, bx);
        float z0f = floorf(fz);
        float x0f = floorf(fx);
        int zi = (int)z0f + 1;       // 0..129 valid (129 row is all-zero guard)
        int xi = (int)x0f + 1;
        if ((unsigned)zi <= 129u && (unsigned)xi <= 129u) {
            float wz = fz - z0f;
            float wx = fx - x0f;
            float4 c = __ldg(&g_C[kbase + zi * BW + xi]);
            float v0 = fmaf(wx, c.y - c.x, c.x);   // lerp over x, row z0
            float v1 = fmaf(wx, c.w - c.z, c.z);   // lerp over x, row z0+1
            acc += fmaf(wz, v1 - v0, v0);          // lerp over z
        }
    }
    out[t] = acc * dxw;
}

// Tail: reference returns (projections, idx); write idx (as float) after the
// projections if the output buffer has room.
__global__ void write_tail_kernel(const int* __restrict__ idx,
                                  float* __restrict__ out, int tail) {
    int t = threadIdx.x;
    if (t < tail) {
        out[NPIX + t] = (t < NPROJ) ? (float)__ldg(&idx[t]) : 0.0f;
    }
}

extern "C" void kernel_launch(void* const* d_in, const int* in_sizes, int n_in,
                              void* d_out, int out_size) {
    const float* vol   = (const float*)d_in[0];   // I_rec: 1*1*128*128*128 f32
    const float* poses = (const float*)d_in[1];   // 50*3 f32
    const int*   idx   = (const int*)d_in[2];     // 10 i32
    float* out = (float*)d_out;

    {
        const int total = DVOL * BPLANE;
        build_C_kernel<<<(total + 255) / 256, 256>>>(vol);
    }
    project_kernel<<<(NPIX + 255) / 256, 256>>>(poses, idx, out);

    if (out_size > NPIX) {
        int tail = out_size - NPIX;
        if (tail > 1024) tail = 1024;
        write_tail_kernel<<<1, 1024>>>(idx, out, tail);
    }
}